// round 6
// baseline (speedup 1.0000x reference)
#include <cuda_runtime.h>

// MultiKR fused forward on GB300 (sm_103a), v3.1: packed f32x2 FFMA2 GEMMs.
//  (re-run of v3 after infra failure; + first weight tile prefetched before
//   the gather barrier)
//  - fma.rn.f32x2: 2 fp32 FMAs per issue slot (FFMA-3reg rt=2 bypass)
//  - k-paired accumulators: A pairs free via 64-bit smem loads, B pairs packed
//    once per k-chunk (amortized over 8 rows)
//  - 512 threads (16 warps), 8x4 microtile, <=128 regs/thread
//  - cp.async double-buffered weight tiles
//
// Inputs (metadata order):
//  0 user_ids int32[16384]  1 item_ids int32[16384]  2 rec_target f32[16384]
//  3 user_tbl f32[100000,128] 4 item_tbl f32[50000,128] 5 entity_tbl f32[50000,128]
//  6-9 w_vv/w_ev/w_ve/w_ee f32[128]  10 bias_v 11 bias_e
// 12 Wu f32[128,128] 13 bu  14 W1 f32[256,256] 15 b1
// 16 W2 f32[256,128] 17 b2  18 W3 f32[128,1]   19 b3
// output: concat(rec_out[16384], rec_target[16384]) f32

#define B_TOT    16384
#define D        128
#define H1       256
#define H2       128
#define TM       128      // rows per CTA
#define NTHREADS 512
#define KT       16       // k-tile rows

// dynamic smem (float offsets)
//  Us   [    0, 16384)
//  Is   [16384, 32768)
//  Hs   [32768, 49152)
//  Ws   [49152, 53248)   two 16x128 weight buffers (2048 floats each)
//  vw   [53248, 53760)
//  dots [53760, 54272)
#define SM_FLOATS 54272

typedef unsigned long long u64;

__device__ __forceinline__ u64 fma2(u64 a, u64 b, u64 c) {
    u64 d;
    asm("fma.rn.f32x2 %0, %1, %2, %3;" : "=l"(d) : "l"(a), "l"(b), "l"(c));
    return d;
}
__device__ __forceinline__ u64 pack2(float lo, float hi) {
    u64 d;
    asm("mov.b64 %0, {%1, %2};" : "=l"(d) : "r"(__float_as_uint(lo)), "r"(__float_as_uint(hi)));
    return d;
}
__device__ __forceinline__ float red2(u64 v) {
    unsigned lo, hi;
    asm("mov.b64 {%0, %1}, %2;" : "=r"(lo), "=r"(hi) : "l"(v));
    return __uint_as_float(lo) + __uint_as_float(hi);
}

__device__ __forceinline__ void cp16(float* dst, const float* src) {
    unsigned s = (unsigned)__cvta_generic_to_shared(dst);
    asm volatile("cp.async.cg.shared.global [%0], [%1], 16;\n" :: "r"(s), "l"(src));
}
#define CP_COMMIT() asm volatile("cp.async.commit_group;\n" ::: "memory")
#define CP_WAIT0()  asm volatile("cp.async.wait_group 0;\n" ::: "memory")

// stage a contiguous 16x128 float tile (2048 floats, 512 threads x 4 floats)
__device__ __forceinline__ void stage_contig(float* dst, const float* src, int tid) {
    cp16(dst + tid * 4, src + tid * 4);
}
// stage W1[k0..k0+15][h*128 .. h*128+127] (row stride 256)
__device__ __forceinline__ void stage_w1(float* dst, const float* W1, int k0, int h, int tid) {
    int rr = tid >> 5, c4 = tid & 31;
    cp16(dst + rr * 128 + c4 * 4, W1 + (k0 + rr) * H1 + h * 128 + c4 * 4);
}

// C[8x4] (k-paired u64 accumulators) += A[8 rows x 16k] * W[16k x 4 cols]
__device__ __forceinline__ void mm_tile(const float* __restrict__ A,
                                        const float* __restrict__ W,
                                        u64 acc[8][4], int r0, int c0, int kbase)
{
    #pragma unroll
    for (int kc = 0; kc < KT; kc += 4) {
        float4 B0 = *(const float4*)(W + (kc + 0) * 128 + c0);
        float4 B1 = *(const float4*)(W + (kc + 1) * 128 + c0);
        float4 B2 = *(const float4*)(W + (kc + 2) * 128 + c0);
        float4 B3 = *(const float4*)(W + (kc + 3) * 128 + c0);
        u64 p0x = pack2(B0.x, B1.x), p0y = pack2(B0.y, B1.y);
        u64 p0z = pack2(B0.z, B1.z), p0w = pack2(B0.w, B1.w);
        u64 p1x = pack2(B2.x, B3.x), p1y = pack2(B2.y, B3.y);
        u64 p1z = pack2(B2.z, B3.z), p1w = pack2(B2.w, B3.w);
        #pragma unroll
        for (int r = 0; r < 8; ++r) {
            ulonglong2 av = *(const ulonglong2*)(A + (r0 + r) * D + kbase + kc);
            acc[r][0] = fma2(av.x, p0x, acc[r][0]);
            acc[r][1] = fma2(av.x, p0y, acc[r][1]);
            acc[r][2] = fma2(av.x, p0z, acc[r][2]);
            acc[r][3] = fma2(av.x, p0w, acc[r][3]);
            acc[r][0] = fma2(av.y, p1x, acc[r][0]);
            acc[r][1] = fma2(av.y, p1y, acc[r][1]);
            acc[r][2] = fma2(av.y, p1z, acc[r][2]);
            acc[r][3] = fma2(av.y, p1w, acc[r][3]);
        }
    }
}

#define ACC_CLEAR(acc)                          \
    _Pragma("unroll")                           \
    for (int r = 0; r < 8; ++r)                 \
        _Pragma("unroll")                       \
        for (int c = 0; c < 4; ++c) acc[r][c] = 0ull;

__global__ __launch_bounds__(NTHREADS, 1)
void multikr_kernel(const int*   __restrict__ user_ids,
                    const int*   __restrict__ item_ids,
                    const float* __restrict__ rec_target,
                    const float* __restrict__ user_tbl,
                    const float* __restrict__ item_tbl,
                    const float* __restrict__ entity_tbl,
                    const float* __restrict__ w_vv,
                    const float* __restrict__ w_ev,
                    const float* __restrict__ w_ve,
                    const float* __restrict__ w_ee,
                    const float* __restrict__ bias_v_p,
                    const float* __restrict__ bias_e_p,
                    const float* __restrict__ Wu,
                    const float* __restrict__ bu,
                    const float* __restrict__ W1,
                    const float* __restrict__ b1,
                    const float* __restrict__ W2,
                    const float* __restrict__ b2,
                    const float* __restrict__ W3,
                    const float* __restrict__ b3,
                    float* __restrict__ out,
                    int out_size)
{
    extern __shared__ float sm[];
    float* Us   = sm;
    float* Is   = sm + 16384;
    float* Hs   = sm + 32768;
    float* Ws   = sm + 49152;          // Ws + 2048 = second buffer
    float* vw   = sm + 53248;
    float* dots = sm + 53760;

    __shared__ int   s_uid[TM];
    __shared__ int   s_iid[TM];
    __shared__ float s_bu[D];
    __shared__ float s_b2[H2];
    __shared__ float s_w3[H2];

    const int tid = threadIdx.x;
    const int b0  = blockIdx.x * TM;

    if (tid < TM) {
        s_uid[tid] = user_ids[b0 + tid];
        s_iid[tid] = item_ids[b0 + tid];
        vw[tid]       = w_vv[tid];
        vw[128 + tid] = w_ev[tid];
        vw[256 + tid] = w_ve[tid];
        vw[384 + tid] = w_ee[tid];
        s_bu[tid] = bu[tid];
        s_b2[tid] = b2[tid];
        s_w3[tid] = W3[tid];
    }

    // prefetch first Wu tile (disjoint smem region; overlaps with gather)
    stage_contig(Ws, Wu, tid); CP_COMMIT();
    __syncthreads();

    // ---- gather embedding rows (coalesced float4) ----
    {
        const float4* ut = (const float4*)user_tbl;
        const float4* it = (const float4*)item_tbl;
        const float4* et = (const float4*)entity_tbl;
        float4* U4 = (float4*)Us;
        float4* I4 = (float4*)Is;
        float4* H4 = (float4*)Hs;
        #pragma unroll
        for (int t = 0; t < (TM * 32) / NTHREADS; ++t) {
            int idx = tid + t * NTHREADS;
            int row = idx >> 5, q = idx & 31;
            U4[idx] = ut[(long)s_uid[row] * 32 + q];
            I4[idx] = it[(long)s_iid[row] * 32 + q];
            H4[idx] = et[(long)s_iid[row] * 32 + q];
        }
    }
    __syncthreads();

    const int r0 = (tid >> 5) * 8;     // warp -> 8 rows (16 warps x 8 = 128)
    const int c0 = (tid & 31) * 4;     // lane -> 4 cols

    const float bias_v = bias_v_p[0];
    const float bias_e = bias_e_p[0];

    // =========================== layer loop ===========================
    for (int layer = 0; layer < 2; ++layer) {
        // ---- user = relu(user @ Wu + bu) ----
        u64 acc[8][4];
        ACC_CLEAR(acc);
        if (layer > 0) { stage_contig(Ws, Wu, tid); CP_COMMIT(); }
        for (int t = 0; t < 8; ++t) {
            CP_WAIT0(); __syncthreads();
            if (t + 1 < 8) { stage_contig(Ws + ((t + 1) & 1) * 2048, Wu + (t + 1) * KT * D, tid); CP_COMMIT(); }
            mm_tile(Us, Ws + (t & 1) * 2048, acc, r0, c0, t * KT);
        }
        __syncthreads();     // readers of Us done -> in-place store OK
        #pragma unroll
        for (int r = 0; r < 8; ++r) {
            float4 v;
            v.x = fmaxf(red2(acc[r][0]) + s_bu[c0 + 0], 0.f);
            v.y = fmaxf(red2(acc[r][1]) + s_bu[c0 + 1], 0.f);
            v.z = fmaxf(red2(acc[r][2]) + s_bu[c0 + 2], 0.f);
            v.w = fmaxf(red2(acc[r][3]) + s_bu[c0 + 3], 0.f);
            *(float4*)(Us + (r0 + r) * D + c0) = v;
        }
        __syncthreads();

        // ---- cross-compress ----
        if (tid < TM) {
            const int row = tid;
            const float* ir = Is + row * D;
            const float* hr = Hs + row * D;
            float hv = 0.f, iv = 0.f, he = 0.f, ie = 0.f;
            #pragma unroll 4
            for (int kk = 0; kk < D; ++kk) {
                int k = (kk + row) & (D - 1);
                float iva = ir[k], hva = hr[k];
                hv = fmaf(hva, vw[k],       hv);
                iv = fmaf(iva, vw[128 + k], iv);
                he = fmaf(hva, vw[256 + k], he);
                ie = fmaf(iva, vw[384 + k], ie);
            }
            dots[row]       = hv;
            dots[128 + row] = iv;
            dots[256 + row] = he;
            dots[384 + row] = ie;
        }
        __syncthreads();
        #pragma unroll
        for (int t = 0; t < (TM * D) / NTHREADS; ++t) {
            int idx = tid + t * NTHREADS;
            int row = idx >> 7;
            float i0 = Is[idx], h0 = Hs[idx];
            float hv = dots[row],       iv = dots[128 + row];
            float he = dots[256 + row], ie = dots[384 + row];
            Is[idx] = fmaf(i0, hv, fmaf(h0, iv, bias_v));
            Hs[idx] = fmaf(i0, he, fmaf(h0, ie, bias_e));
        }
        __syncthreads();
    }

    // ================= MLP =================
    // h1 half h: relu([U|I] @ W1[:, h*128:(h+1)*128] + b1_half)
    //   h=0 -> Hs (head acts dead), h=1 -> Us (user acts dead after its GEMM)
    for (int h = 0; h < 2; ++h) {
        u64 acc[8][4];
        ACC_CLEAR(acc);
        stage_w1(Ws, W1, 0, h, tid); CP_COMMIT();
        for (int t = 0; t < 16; ++t) {
            CP_WAIT0(); __syncthreads();
            if (t + 1 < 16) { stage_w1(Ws + ((t + 1) & 1) * 2048, W1, (t + 1) * KT, h, tid); CP_COMMIT(); }
            const float* Asrc = (t < 8) ? Us : Is;
            mm_tile(Asrc, Ws + (t & 1) * 2048, acc, r0, c0, (t * KT) & (D - 1));
        }
        __syncthreads();     // all reads of Us/Is/dest complete
        float* Dst = (h == 0) ? Hs : Us;
        {
            float4 b1v = *(const float4*)(b1 + h * 128 + c0);
            #pragma unroll
            for (int r = 0; r < 8; ++r) {
                float4 v;
                v.x = fmaxf(red2(acc[r][0]) + b1v.x, 0.f);
                v.y = fmaxf(red2(acc[r][1]) + b1v.y, 0.f);
                v.z = fmaxf(red2(acc[r][2]) + b1v.z, 0.f);
                v.w = fmaxf(red2(acc[r][3]) + b1v.w, 0.f);
                *(float4*)(Dst + (r0 + r) * D + c0) = v;
            }
        }
        __syncthreads();
    }

    // h2 = relu(h1 @ W2 + b2), h1 = [Hs | Us] over K=256 -> store into Is (dead)
    {
        u64 acc[8][4];
        ACC_CLEAR(acc);
        stage_contig(Ws, W2, tid); CP_COMMIT();
        for (int t = 0; t < 16; ++t) {
            CP_WAIT0(); __syncthreads();
            if (t + 1 < 16) { stage_contig(Ws + ((t + 1) & 1) * 2048, W2 + (t + 1) * KT * H2, tid); CP_COMMIT(); }
            const float* Asrc = (t < 8) ? Hs : Us;
            mm_tile(Asrc, Ws + (t & 1) * 2048, acc, r0, c0, (t * KT) & (D - 1));
        }
        __syncthreads();     // prior phase readers done
        #pragma unroll
        for (int r = 0; r < 8; ++r) {
            float4 v;
            v.x = fmaxf(red2(acc[r][0]) + s_b2[c0 + 0], 0.f);
            v.y = fmaxf(red2(acc[r][1]) + s_b2[c0 + 1], 0.f);
            v.z = fmaxf(red2(acc[r][2]) + s_b2[c0 + 2], 0.f);
            v.w = fmaxf(red2(acc[r][3]) + s_b2[c0 + 3], 0.f);
            *(float4*)(Is + (r0 + r) * D + c0) = v;
        }
        __syncthreads();
    }

    // out = relu(h2 @ W3 + b3)
    if (tid < TM) {
        const int row = tid;
        const float* hr = Is + row * D;
        float d = 0.f;
        #pragma unroll 4
        for (int kk = 0; kk < D; ++kk) {
            int k = (kk + row) & (D - 1);
            d = fmaf(hr[k], s_w3[k], d);
        }
        out[b0 + row] = fmaxf(d + b3[0], 0.f);
        if (out_size >= 2 * B_TOT)
            out[B_TOT + b0 + row] = rec_target[b0 + row];
    }
}

extern "C" void kernel_launch(void* const* d_in, const int* in_sizes, int n_in,
                              void* d_out, int out_size)
{
    (void)n_in; (void)in_sizes;
    const int*   user_ids   = (const int*)  d_in[0];
    const int*   item_ids   = (const int*)  d_in[1];
    const float* rec_target = (const float*)d_in[2];
    const float* user_tbl   = (const float*)d_in[3];
    const float* item_tbl   = (const float*)d_in[4];
    const float* entity_tbl = (const float*)d_in[5];
    const float* w_vv   = (const float*)d_in[6];
    const float* w_ev   = (const float*)d_in[7];
    const float* w_ve   = (const float*)d_in[8];
    const float* w_ee   = (const float*)d_in[9];
    const float* bias_v = (const float*)d_in[10];
    const float* bias_e = (const float*)d_in[11];
    const float* Wu = (const float*)d_in[12];
    const float* bu = (const float*)d_in[13];
    const float* W1 = (const float*)d_in[14];
    const float* b1 = (const float*)d_in[15];
    const float* W2 = (const float*)d_in[16];
    const float* b2 = (const float*)d_in[17];
    const float* W3 = (const float*)d_in[18];
    const float* b3 = (const float*)d_in[19];

    const size_t smem = SM_FLOATS * sizeof(float);   // ~212 KB
    cudaFuncSetAttribute(multikr_kernel,
                         cudaFuncAttributeMaxDynamicSharedMemorySize, (int)smem);

    multikr_kernel<<<B_TOT / TM, NTHREADS, smem>>>(
        user_ids, item_ids, rec_target, user_tbl, item_tbl, entity_tbl,
        w_vv, w_ev, w_ve, w_ee, bias_v, bias_e,
        Wu, bu, W1, b1, W2, b2, W3, b3,
        (float*)d_out, out_size);
}

// round 7
// speedup vs baseline: 1.6780x; 1.6780x over previous
#include <cuda_runtime.h>

// MultiKR fused forward on GB300 (sm_103a), v4: tf32 tensor-core GEMMs
// with 3-term (tf32x3) split for fp32-grade accuracy.
//  - mma.sync.aligned.m16n8k8 tf32, fp32 accumulate
//  - weights pre-split (hi/lo) and pre-packed in fragment order by a tiny
//    converter kernel into __device__ scratch (legal scratch per harness rules)
//  - activations fp32 in smem (stride 132 padding -> conflict-free frags),
//    rna-converted to tf32 at fragment load
//  - cp.async double-buffered 8-row weight k-tiles
//
// Inputs (metadata order):
//  0 user_ids int32[16384]  1 item_ids int32[16384]  2 rec_target f32[16384]
//  3 user_tbl f32[100000,128] 4 item_tbl f32[50000,128] 5 entity_tbl f32[50000,128]
//  6-9 w_vv/w_ev/w_ve/w_ee f32[128]  10 bias_v 11 bias_e
// 12 Wu f32[128,128] 13 bu  14 W1 f32[256,256] 15 b1
// 16 W2 f32[256,128] 17 b2  18 W3 f32[128,1]   19 b3
// output: concat(rec_out[16384], rec_target[16384]) f32

#define B_TOT    16384
#define D        128
#define H1       256
#define H2       128
#define TM       128          // rows per CTA
#define NTHREADS 256
#define AST      132          // activation smem row stride (floats), conflict-free

// dynamic smem (float offsets)
//  Us   [     0, 16896)
//  Is   [ 16896, 33792)
//  Hs   [ 33792, 50688)
//  Ws   [ 50688, 54784)   two k-tile buffers x 2048 floats (hi 1024 | lo 1024)
//  vw   [ 54784, 55296)
//  dots [ 55296, 55808)
#define SM_FLOATS 55808

// ---- fragment-packed split weights (written by converter kernel each launch)
// layout per k-step tile t (k = 8 rows): 2048 floats = [hi: j(16) x lane(32) x p(2)][lo: same]
__device__ float g_cWu[16 * 2048];            //  Wu: K=128 -> 16 tiles
__device__ float g_cW1[2 * 32 * 2048];        //  W1 halves: K=256 -> 32 tiles each
__device__ float g_cW2[32 * 2048];            //  W2: K=256 -> 32 tiles

__device__ __forceinline__ unsigned tf32u(float x) {
    unsigned u;
    asm("cvt.rna.tf32.f32 %0, %1;" : "=r"(u) : "f"(x));
    return u;
}
__device__ __forceinline__ float tf32f(float x) { return __uint_as_float(tf32u(x)); }

__global__ void convert_weights_kernel(const float* __restrict__ Wu,
                                       const float* __restrict__ W1,
                                       const float* __restrict__ W2)
{
    int i = blockIdx.x * blockDim.x + threadIdx.x;
    if (i >= 16384 + 65536 + 32768) return;
    float w; float* base; int k, n;
    if (i < 16384)      { k = i >> 7;  n = i & 127;  w = Wu[i]; base = g_cWu; }
    else if (i < 81920) { int s = i - 16384; k = s >> 8; int nf = s & 255;
                          w = W1[s]; base = g_cW1 + (nf >> 7) * (32 * 2048); n = nf & 127; }
    else                { int s = i - 81920; k = s >> 7; n = s & 127; w = W2[s]; base = g_cW2; }
    // fragment mapping for mma.m16n8k8 .col B: b0 k=lane%4, b1 k=lane%4+4, n=lane/4
    int t = k >> 3, p = (k >> 2) & 1, km = k & 3;
    int j = n >> 3, l = (n & 7) * 4 + km;
    int off = t * 2048 + j * 64 + l * 2 + p;
    float hi = tf32f(w);
    float lo = tf32f(w - hi);
    base[off]        = hi;
    base[off + 1024] = lo;
}

// ---- cp.async helpers ----
__device__ __forceinline__ void cp16(float* dst, const float* src) {
    unsigned s = (unsigned)__cvta_generic_to_shared(dst);
    asm volatile("cp.async.cg.shared.global [%0], [%1], 16;\n" :: "r"(s), "l"(src));
}
#define CP_COMMIT() asm volatile("cp.async.commit_group;\n" ::: "memory")
#define CP_WAIT0()  asm volatile("cp.async.wait_group 0;\n" ::: "memory")

// stage one 2048-float packed tile (256 threads x 2 cp16)
__device__ __forceinline__ void stage8(float* dst, const float* src, int tid) {
    cp16(dst + tid * 4,        src + tid * 4);
    cp16(dst + 1024 + tid * 4, src + 1024 + tid * 4);
}

__device__ __forceinline__ void mma8(float acc[4],
                                     unsigned a0, unsigned a1, unsigned a2, unsigned a3,
                                     unsigned b0, unsigned b1)
{
    asm("mma.sync.aligned.m16n8k8.row.col.f32.tf32.tf32.f32 "
        "{%0,%1,%2,%3},{%4,%5,%6,%7},{%8,%9},{%0,%1,%2,%3};"
        : "+f"(acc[0]), "+f"(acc[1]), "+f"(acc[2]), "+f"(acc[3])
        : "r"(a0), "r"(a1), "r"(a2), "r"(a3), "r"(b0), "r"(b1));
}

// GEMM: C[TM x 128] += A[TM x 8*ksteps] * W, A = [A0 | A1] switching at tswitch.
// Warp covers 16 rows; 16 n-tiles of 8. 3-term tf32 split.
__device__ __forceinline__ void gemm_tf32(const float* __restrict__ A0,
                                          const float* __restrict__ A1, int tswitch,
                                          const float* __restrict__ Wsrc, int ksteps,
                                          float* Ws, int tid, int lane, int r0,
                                          float acc[16][4], bool prefetched)
{
    if (!prefetched) { stage8(Ws, Wsrc, tid); CP_COMMIT(); }
    for (int t = 0; t < ksteps; ++t) {
        CP_WAIT0(); __syncthreads();
        if (t + 1 < ksteps) { stage8(Ws + ((t + 1) & 1) * 2048, Wsrc + (t + 1) * 2048, tid); CP_COMMIT(); }
        const float* A = (t < tswitch) ? A0 : A1;
        const int kk = (t * 8) & 127;
        const int ra = (r0 + (lane >> 2)) * AST + kk + (lane & 3);
        float a0f = A[ra];
        float a1f = A[ra + 8 * AST];
        float a2f = A[ra + 4];
        float a3f = A[ra + 8 * AST + 4];
        unsigned ah0 = tf32u(a0f), ah1 = tf32u(a1f), ah2 = tf32u(a2f), ah3 = tf32u(a3f);
        unsigned al0 = tf32u(a0f - __uint_as_float(ah0));
        unsigned al1 = tf32u(a1f - __uint_as_float(ah1));
        unsigned al2 = tf32u(a2f - __uint_as_float(ah2));
        unsigned al3 = tf32u(a3f - __uint_as_float(ah3));
        const float* Wb = Ws + (t & 1) * 2048;
        #pragma unroll
        for (int j = 0; j < 16; ++j) {
            float2 bh = *(const float2*)(Wb + j * 64 + lane * 2);
            float2 bl = *(const float2*)(Wb + 1024 + j * 64 + lane * 2);
            unsigned bh0 = __float_as_uint(bh.x), bh1 = __float_as_uint(bh.y);
            unsigned bl0 = __float_as_uint(bl.x), bl1 = __float_as_uint(bl.y);
            mma8(acc[j], ah0, ah1, ah2, ah3, bh0, bh1);
            mma8(acc[j], al0, al1, al2, al3, bh0, bh1);
            mma8(acc[j], ah0, ah1, ah2, ah3, bl0, bl1);
        }
    }
}

__device__ __forceinline__ void acc_clear(float acc[16][4]) {
    #pragma unroll
    for (int j = 0; j < 16; ++j)
        #pragma unroll
        for (int c = 0; c < 4; ++c) acc[j][c] = 0.f;
}

// relu(acc + bias) -> Dst (stride AST)
__device__ __forceinline__ void epilogue(float acc[16][4], float* Dst,
                                         const float* bias, int lane, int r0)
{
    const int row = r0 + (lane >> 2);
    const int cb  = 2 * (lane & 3);
    #pragma unroll
    for (int j = 0; j < 16; ++j) {
        int col = 8 * j + cb;
        float2 v0, v1;
        v0.x = fmaxf(acc[j][0] + bias[col],     0.f);
        v0.y = fmaxf(acc[j][1] + bias[col + 1], 0.f);
        v1.x = fmaxf(acc[j][2] + bias[col],     0.f);
        v1.y = fmaxf(acc[j][3] + bias[col + 1], 0.f);
        *(float2*)(Dst + row * AST + col)       = v0;
        *(float2*)(Dst + (row + 8) * AST + col) = v1;
    }
}

__global__ __launch_bounds__(NTHREADS, 1)
void multikr_kernel(const int*   __restrict__ user_ids,
                    const int*   __restrict__ item_ids,
                    const float* __restrict__ rec_target,
                    const float* __restrict__ user_tbl,
                    const float* __restrict__ item_tbl,
                    const float* __restrict__ entity_tbl,
                    const float* __restrict__ w_vv,
                    const float* __restrict__ w_ev,
                    const float* __restrict__ w_ve,
                    const float* __restrict__ w_ee,
                    const float* __restrict__ bias_v_p,
                    const float* __restrict__ bias_e_p,
                    const float* __restrict__ bu,
                    const float* __restrict__ b1,
                    const float* __restrict__ b2,
                    const float* __restrict__ W3,
                    const float* __restrict__ b3,
                    float* __restrict__ out,
                    int out_size)
{
    extern __shared__ float sm[];
    float* Us   = sm;
    float* Is   = sm + 16896;
    float* Hs   = sm + 33792;
    float* Ws   = sm + 50688;
    float* vw   = sm + 54784;
    float* dots = sm + 55296;

    __shared__ int   s_uid[TM];
    __shared__ int   s_iid[TM];
    __shared__ float s_bu[D];
    __shared__ float s_b1[H1];
    __shared__ float s_b2[H2];
    __shared__ float s_w3[H2];

    const int tid  = threadIdx.x;
    const int lane = tid & 31;
    const int r0   = (tid >> 5) * 16;    // warp -> 16 rows
    const int b0   = blockIdx.x * TM;

    if (tid < TM) {
        s_uid[tid] = user_ids[b0 + tid];
        s_iid[tid] = item_ids[b0 + tid];
        vw[tid]       = w_vv[tid];
        vw[128 + tid] = w_ev[tid];
        vw[256 + tid] = w_ve[tid];
        vw[384 + tid] = w_ee[tid];
        s_bu[tid] = bu[tid];
        s_b2[tid] = b2[tid];
        s_w3[tid] = W3[tid];
    }
    if (tid < H1) s_b1[tid] = b1[tid];

    // prefetch first Wu tile (Ws disjoint; overlaps with the gather)
    stage8(Ws, g_cWu, tid); CP_COMMIT();
    __syncthreads();

    // ---- gather embedding rows (coalesced float4, stride AST) ----
    {
        const float4* ut = (const float4*)user_tbl;
        const float4* it = (const float4*)item_tbl;
        const float4* et = (const float4*)entity_tbl;
        float4* U4 = (float4*)Us;
        float4* I4 = (float4*)Is;
        float4* H4 = (float4*)Hs;
        #pragma unroll
        for (int t = 0; t < (TM * 32) / NTHREADS; ++t) {
            int idx = tid + t * NTHREADS;
            int row = idx >> 5, q = idx & 31;
            U4[row * (AST / 4) + q] = ut[(long)s_uid[row] * 32 + q];
            I4[row * (AST / 4) + q] = it[(long)s_iid[row] * 32 + q];
            H4[row * (AST / 4) + q] = et[(long)s_iid[row] * 32 + q];
        }
    }
    __syncthreads();

    const float bias_v = bias_v_p[0];
    const float bias_e = bias_e_p[0];

    float acc[16][4];

    // =========================== layer loop ===========================
    for (int layer = 0; layer < 2; ++layer) {
        // ---- user = relu(user @ Wu + bu) ----
        acc_clear(acc);
        gemm_tf32(Us, Us, 16, g_cWu, 16, Ws, tid, lane, r0, acc, layer == 0);
        __syncthreads();                 // all reads of Us done
        epilogue(acc, Us, s_bu, lane, r0);
        __syncthreads();

        // ---- cross-compress ----
        if (tid < TM) {
            const int row = tid;
            const float* ir = Is + row * AST;
            const float* hr = Hs + row * AST;
            float hv = 0.f, iv = 0.f, he = 0.f, ie = 0.f;
            #pragma unroll 4
            for (int kk = 0; kk < D; ++kk) {
                int k = (kk + row) & (D - 1);
                float iva = ir[k], hva = hr[k];
                hv = fmaf(hva, vw[k],       hv);
                iv = fmaf(iva, vw[128 + k], iv);
                he = fmaf(hva, vw[256 + k], he);
                ie = fmaf(iva, vw[384 + k], ie);
            }
            dots[row]       = hv;
            dots[128 + row] = iv;
            dots[256 + row] = he;
            dots[384 + row] = ie;
        }
        __syncthreads();
        #pragma unroll 8
        for (int t = 0; t < (TM * D) / NTHREADS; ++t) {
            int idx = tid + t * NTHREADS;
            int row = idx >> 7, col = idx & 127;
            int a = row * AST + col;
            float i0 = Is[a], h0 = Hs[a];
            float hv = dots[row],       iv = dots[128 + row];
            float he = dots[256 + row], ie = dots[384 + row];
            Is[a] = fmaf(i0, hv, fmaf(h0, iv, bias_v));
            Hs[a] = fmaf(i0, he, fmaf(h0, ie, bias_e));
        }
        __syncthreads();
    }

    // ================= MLP =================
    // h1 half0 -> Hs (head acts dead), half1 -> Us (user acts dead after reads)
    acc_clear(acc);
    gemm_tf32(Us, Is, 16, g_cW1, 32, Ws, tid, lane, r0, acc, false);
    __syncthreads();
    epilogue(acc, Hs, s_b1, lane, r0);
    __syncthreads();

    acc_clear(acc);
    gemm_tf32(Us, Is, 16, g_cW1 + 32 * 2048, 32, Ws, tid, lane, r0, acc, false);
    __syncthreads();
    epilogue(acc, Us, s_b1 + 128, lane, r0);
    __syncthreads();

    // h2 = relu([Hs|Us] @ W2 + b2) -> Is (item acts dead)
    acc_clear(acc);
    gemm_tf32(Hs, Us, 16, g_cW2, 32, Ws, tid, lane, r0, acc, false);
    __syncthreads();
    epilogue(acc, Is, s_b2, lane, r0);
    __syncthreads();

    // out = relu(h2 @ W3 + b3)
    if (tid < TM) {
        const int row = tid;
        const float* hr = Is + row * AST;
        float d = 0.f;
        #pragma unroll 4
        for (int kk = 0; kk < D; ++kk) {
            int k = (kk + row) & (D - 1);
            d = fmaf(hr[k], s_w3[k], d);
        }
        out[b0 + row] = fmaxf(d + b3[0], 0.f);
        if (out_size >= 2 * B_TOT)
            out[B_TOT + b0 + row] = rec_target[b0 + row];
    }
}

extern "C" void kernel_launch(void* const* d_in, const int* in_sizes, int n_in,
                              void* d_out, int out_size)
{
    (void)n_in; (void)in_sizes;
    const int*   user_ids   = (const int*)  d_in[0];
    const int*   item_ids   = (const int*)  d_in[1];
    const float* rec_target = (const float*)d_in[2];
    const float* user_tbl   = (const float*)d_in[3];
    const float* item_tbl   = (const float*)d_in[4];
    const float* entity_tbl = (const float*)d_in[5];
    const float* w_vv   = (const float*)d_in[6];
    const float* w_ev   = (const float*)d_in[7];
    const float* w_ve   = (const float*)d_in[8];
    const float* w_ee   = (const float*)d_in[9];
    const float* bias_v = (const float*)d_in[10];
    const float* bias_e = (const float*)d_in[11];
    const float* Wu = (const float*)d_in[12];
    const float* bu = (const float*)d_in[13];
    const float* W1 = (const float*)d_in[14];
    const float* b1 = (const float*)d_in[15];
    const float* W2 = (const float*)d_in[16];
    const float* b2 = (const float*)d_in[17];
    const float* W3 = (const float*)d_in[18];
    const float* b3 = (const float*)d_in[19];

    // 1) split + fragment-pack the weights (deterministic, graph-capturable)
    convert_weights_kernel<<<(16384 + 65536 + 32768 + 255) / 256, 256>>>(Wu, W1, W2);

    // 2) fused forward
    const size_t smem = SM_FLOATS * sizeof(float);   // ~218 KB
    cudaFuncSetAttribute(multikr_kernel,
                         cudaFuncAttributeMaxDynamicSharedMemorySize, (int)smem);
    multikr_kernel<<<B_TOT / TM, NTHREADS, smem>>>(
        user_ids, item_ids, rec_target, user_tbl, item_tbl, entity_tbl,
        w_vv, w_ev, w_ve, w_ee, bias_v, bias_e,
        bu, b1, b2, W3, b3,
        (float*)d_out, out_size);
}